// round 6
// baseline (speedup 1.0000x reference)
#include <cuda_runtime.h>
#include <math.h>
#include <stdint.h>

// ---- problem constants ----
#define BB    2
#define HIDN  2048
#define NHH   16
#define LLN   8
#define VV    32000
#define DDIM  128
#define OFFN  1024
#define RRES  1025
#define PHEAP 11272
#define NK    2049
#define FFN   8192
#define SSEQ  2048
#define NCHUNK 17

// ---- device scratch (allocation-free) ----
__device__ __align__(16) float g_x [BB][HIDN];
__device__ __align__(16) float g_q [BB][NHH][DDIM];
__device__ __align__(16) float g_kscr[LLN][BB][NHH][DDIM];
__device__ __align__(16) float g_vscr[LLN][BB][NHH][DDIM];
__device__ __align__(16) float g_h[BB][FFN];
__device__ float g_pm[NCHUNK][BB * NHH];
__device__ float g_ps[NCHUNK][BB * NHH];
__device__ __align__(16) float g_po[NCHUNK][BB * NHH][DDIM];
__device__ unsigned int g_cnt[BB * NHH];   // zero-init; self-resetting

// ============================================================
// x = x + sinusoidal PE(pos)
// ============================================================
__global__ void k_init(const float* __restrict__ x, const int* __restrict__ posp) {
    int b = blockIdx.x;
    float pos = (float)(*posp);
    for (int e = threadIdx.x; e < HIDN; e += blockDim.x) {
        int i = e >> 1;
        float div = expf(-logf(10000.0f) * (2.0f * (float)i) / (float)HIDN);
        float ang = pos * div;
        float pe = (e & 1) ? cosf(ang) : sinf(ang);
        g_x[b][e] = x[(size_t)b * HIDN + e] + pe;
    }
}

// ============================================================
// LN prologue (warp-shuffle, 3 barriers). block = 256 threads.
// xs layout: [0,512) = batch0 float4, [512,1024) = batch1 float4.
// ============================================================
__device__ __forceinline__ void stage_ln(float4* xs,
                                         const float* __restrict__ gam,
                                         const float* __restrict__ bet) {
    int tid = threadIdx.x, lane = tid & 31, warp = tid >> 5;
    __shared__ float4 wred[8];
    __shared__ float4 stats;   // mean0, rstd0, mean1, rstd1
    const float4* x0 = (const float4*)g_x[0];
    const float4* x1 = (const float4*)g_x[1];
    float4 a0 = x0[tid], a1 = x0[tid + 256];
    float4 b0 = x1[tid], b1 = x1[tid + 256];
    float s0 = a0.x + a0.y + a0.z + a0.w + a1.x + a1.y + a1.z + a1.w;
    float s1 = b0.x + b0.y + b0.z + b0.w + b1.x + b1.y + b1.z + b1.w;
    float q0 = a0.x*a0.x + a0.y*a0.y + a0.z*a0.z + a0.w*a0.w
             + a1.x*a1.x + a1.y*a1.y + a1.z*a1.z + a1.w*a1.w;
    float q1 = b0.x*b0.x + b0.y*b0.y + b0.z*b0.z + b0.w*b0.w
             + b1.x*b1.x + b1.y*b1.y + b1.z*b1.z + b1.w*b1.w;
    #pragma unroll
    for (int off = 16; off > 0; off >>= 1) {
        s0 += __shfl_down_sync(0xffffffffu, s0, off);
        q0 += __shfl_down_sync(0xffffffffu, q0, off);
        s1 += __shfl_down_sync(0xffffffffu, s1, off);
        q1 += __shfl_down_sync(0xffffffffu, q1, off);
    }
    if (lane == 0) wred[warp] = make_float4(s0, q0, s1, q1);
    __syncthreads();
    if (warp == 0) {
        float4 v = wred[lane & 7];
        float t0 = v.x, t1 = v.y, t2 = v.z, t3 = v.w;
        #pragma unroll
        for (int off = 4; off > 0; off >>= 1) {
            t0 += __shfl_down_sync(0xffffffffu, t0, off, 8);
            t1 += __shfl_down_sync(0xffffffffu, t1, off, 8);
            t2 += __shfl_down_sync(0xffffffffu, t2, off, 8);
            t3 += __shfl_down_sync(0xffffffffu, t3, off, 8);
        }
        if (lane == 0) {
            float mean0 = t0 * (1.0f / HIDN);
            float mean1 = t2 * (1.0f / HIDN);
            float var0  = t1 * (1.0f / HIDN) - mean0 * mean0;
            float var1  = t3 * (1.0f / HIDN) - mean1 * mean1;
            stats = make_float4(mean0, rsqrtf(var0 + 1e-5f),
                                mean1, rsqrtf(var1 + 1e-5f));
        }
    }
    __syncthreads();
    float4 st = stats;
    const float4* g4 = (const float4*)gam;
    const float4* e4 = (const float4*)bet;
    float4 ga = g4[tid], gb = g4[tid + 256];
    float4 ea = e4[tid], eb = e4[tid + 256];
    xs[tid] = make_float4((a0.x - st.x) * st.y * ga.x + ea.x,
                          (a0.y - st.x) * st.y * ga.y + ea.y,
                          (a0.z - st.x) * st.y * ga.z + ea.z,
                          (a0.w - st.x) * st.y * ga.w + ea.w);
    xs[tid + 256] = make_float4((a1.x - st.x) * st.y * gb.x + eb.x,
                                (a1.y - st.x) * st.y * gb.y + eb.y,
                                (a1.z - st.x) * st.y * gb.z + eb.z,
                                (a1.w - st.x) * st.y * gb.w + eb.w);
    xs[512 + tid] = make_float4((b0.x - st.z) * st.w * ga.x + ea.x,
                                (b0.y - st.z) * st.w * ga.y + ea.y,
                                (b0.z - st.z) * st.w * ga.z + ea.z,
                                (b0.w - st.z) * st.w * ga.w + ea.w);
    xs[512 + tid + 256] = make_float4((b1.x - st.z) * st.w * gb.x + eb.x,
                                      (b1.y - st.z) * st.w * gb.y + eb.y,
                                      (b1.z - st.z) * st.w * gb.z + eb.z,
                                      (b1.w - st.z) * st.w * gb.w + eb.w);
    __syncthreads();
}

// ============================================================
// dual-row warp GEMV: two weight rows vs two smem vectors
// returns (rowA·x0, rowA·x1, rowB·x0, rowB·x1)
// ============================================================
template <int N4>
__device__ __forceinline__ float4 dot4_smem(const float4* __restrict__ wa,
                                            const float4* __restrict__ wb,
                                            const float4* xs, int lane) {
    float a0 = 0.f, a1 = 0.f, c0 = 0.f, c1 = 0.f;
    #pragma unroll 4
    for (int i = lane; i < N4; i += 32) {
        float4 p = wa[i];
        float4 q = wb[i];
        float4 u = xs[i];
        float4 v = xs[N4 + i];
        a0 += p.x*u.x + p.y*u.y + p.z*u.z + p.w*u.w;
        a1 += p.x*v.x + p.y*v.y + p.z*v.z + p.w*v.w;
        c0 += q.x*u.x + q.y*u.y + q.z*u.z + q.w*u.w;
        c1 += q.x*v.x + q.y*v.y + q.z*v.z + q.w*v.w;
    }
    #pragma unroll
    for (int off = 16; off > 0; off >>= 1) {
        a0 += __shfl_down_sync(0xffffffffu, a0, off);
        a1 += __shfl_down_sync(0xffffffffu, a1, off);
        c0 += __shfl_down_sync(0xffffffffu, c0, off);
        c1 += __shfl_down_sync(0xffffffffu, c1, off);
    }
    return make_float4(a0, a1, c0, c1);
}

__device__ __forceinline__ void route_qkv(int j, float v0, float v1, int l) {
    int h = j / 384, c = j % 384;
    if (c < 128)      { g_q[0][h][c] = v0;             g_q[1][h][c] = v1; }
    else if (c < 256) { g_kscr[l][0][h][c-128] = v0;   g_kscr[l][1][h][c-128] = v1; }
    else              { g_vscr[l][0][h][c-256] = v0;   g_vscr[l][1][h][c-256] = v1; }
}

// ============================================================
// QKV projection (LN fused): 6144 rows, 16 rows/block
// ============================================================
__global__ void __launch_bounds__(256, 4)
k_qkv(const float* __restrict__ qkv_w,
      const float* __restrict__ gam, const float* __restrict__ bet, int l) {
    __shared__ __align__(16) float4 xs[1024];
    stage_ln(xs, gam, bet);
    int warp = threadIdx.x >> 5, lane = threadIdx.x & 31;
    int j = blockIdx.x * 16 + warp * 2;
    const float4* wa = (const float4*)(qkv_w + ((size_t)l * 3 * HIDN + j) * HIDN);
    const float4* wb = wa + 512;
    float4 r = dot4_smem<512>(wa, wb, xs, lane);
    if (lane == 0) {
        route_qkv(j,     r.x, r.y, l);
        route_qkv(j + 1, r.z, r.w, l);
    }
}

// ============================================================
// KV row addressing with scatter-write overrides
// ============================================================
__device__ __forceinline__ const float* kv_row(int l, int b, int h, int k,
        const float* __restrict__ heap, const float* __restrict__ off,
        const float (*scr)[BB][NHH][DDIM]) {
    if (l == 0) {
        if (k == SSEQ) return scr[0][b][h];
        return heap + (((size_t)(b * NHH + h)) * PHEAP + (size_t)k) * DDIM;
    }
    if (k < RRES) {
        if (k == 1023 && l >= 2) return scr[l - 2][b][h];
        return heap + (((size_t)(b * NHH + h)) * PHEAP + (size_t)(l - 1) * RRES + (size_t)k) * DDIM;
    }
    return off + (((((size_t)(l - 1)) * BB + b) * NHH + h) * OFFN + (size_t)(k - RRES)) * DDIM;
}

// ============================================================
// fused flash-decode partial + last-block combine
// grid (17, 32), block 256
// ============================================================
__global__ void k_flash(const float* __restrict__ kh, const float* __restrict__ ko,
                        const float* __restrict__ vh, const float* __restrict__ vo, int l) {
    int bh = blockIdx.y; int b = bh >> 4, h = bh & 15;
    int base = blockIdx.x * 128;
    int tid = threadIdx.x, warp = tid >> 5, lane = tid & 31;
    __shared__ float part[128][33];
    __shared__ float sc[128];
    __shared__ float red[128];
    __shared__ __align__(16) float4 vred[8][32];
    __shared__ __align__(16) float q_s[DDIM];
    __shared__ bool is_last;
    if (tid < DDIM) q_s[tid] = g_q[b][h][tid];
    __syncthreads();
    float4 q4 = ((const float4*)q_s)[lane];

    // ---- K phase: warp handles 16 independent rows ----
    #pragma unroll 4
    for (int i = 0; i < 16; i++) {
        int r = warp * 16 + i, k = base + r;
        float p = 0.f;
        if (k < NK) {
            const float* kr = kv_row(l, b, h, k, kh, ko, g_kscr);
            float4 kk = ((const float4*)kr)[lane];
            p = q4.x*kk.x + q4.y*kk.y + q4.z*kk.z + q4.w*kk.w;
        }
        part[r][lane] = p;
    }
    __syncthreads();

    // ---- score reduce (conflict-free, stride 33) ----
    if (tid < 128) {
        float s = 0.f;
        #pragma unroll
        for (int i = 0; i < 32; i++) s += part[tid][i];
        s *= 0.088388347648318447f;
        if (base + tid >= NK) s = -1e30f;
        sc[tid] = s;
    }
    __syncthreads();
    if (tid < 64) red[tid] = fmaxf(sc[tid], sc[tid + 64]);
    __syncthreads();
    if (tid < 32) {
        float m = fmaxf(red[tid], red[tid + 32]);
        #pragma unroll
        for (int off = 16; off > 0; off >>= 1)
            m = fmaxf(m, __shfl_down_sync(0xffffffffu, m, off));
        if (tid == 0) red[0] = m;
    }
    __syncthreads();
    float mloc = red[0];
    __syncthreads();
    if (tid < 128) sc[tid] = expf(sc[tid] - mloc);
    __syncthreads();
    if (tid < 64) red[tid] = sc[tid] + sc[tid + 64];
    __syncthreads();
    if (tid < 32) {
        float s = red[tid] + red[tid + 32];
        #pragma unroll
        for (int off = 16; off > 0; off >>= 1)
            s += __shfl_down_sync(0xffffffffu, s, off);
        if (tid == 0) red[0] = s;
    }
    __syncthreads();
    float ssum = red[0];

    // ---- V phase ----
    float4 acc = make_float4(0.f, 0.f, 0.f, 0.f);
    #pragma unroll 4
    for (int i = 0; i < 16; i++) {
        int r = warp * 16 + i, k = base + r;
        if (k < NK) {
            const float* vr = kv_row(l, b, h, k, vh, vo, g_vscr);
            float4 v4 = ((const float4*)vr)[lane];
            float pr = sc[r];
            acc.x += pr * v4.x; acc.y += pr * v4.y;
            acc.z += pr * v4.z; acc.w += pr * v4.w;
        }
    }
    vred[warp][lane] = acc;
    __syncthreads();
    if (tid < 128) {
        int li = tid >> 2, c = tid & 3;
        float o = 0.f;
        #pragma unroll
        for (int w2 = 0; w2 < 8; w2++) o += ((const float*)&vred[w2][li])[c];
        g_po[blockIdx.x][bh][tid] = o;
    }
    if (tid == 0) { g_pm[blockIdx.x][bh] = mloc; g_ps[blockIdx.x][bh] = ssum; }

    // ---- last block for this (b,h) combines all 17 partials ----
    __threadfence();
    if (tid == 0) {
        unsigned int v = atomicAdd(&g_cnt[bh], 1u);
        is_last = (v == NCHUNK - 1);
    }
    __syncthreads();
    if (!is_last) return;
    __threadfence();                    // acquire partials from other blocks
    if (tid == 0) g_cnt[bh] = 0;        // reset for next layer / graph replay
    if (tid < 128) {
        float m = -1e30f;
        #pragma unroll
        for (int c = 0; c < NCHUNK; c++) m = fmaxf(m, g_pm[c][bh]);
        float S = 0.f, o = 0.f;
        #pragma unroll
        for (int c = 0; c < NCHUNK; c++) {
            float w = expf(g_pm[c][bh] - m);
            S += g_ps[c][bh] * w;
            o += g_po[c][bh][tid] * w;
        }
        g_x[b][h * DDIM + tid] += o / S;
    }
}

// ============================================================
// FFN
// ============================================================
__device__ __forceinline__ float gelu_exact(float x) {
    return 0.5f * x * (1.0f + erff(x * 0.70710678118654752f));
}

__global__ void __launch_bounds__(256, 4)
k_ffn1(const float* __restrict__ w,
       const float* __restrict__ gam, const float* __restrict__ bet, int l) {
    __shared__ __align__(16) float4 xs[1024];
    stage_ln(xs, gam, bet);
    int warp = threadIdx.x >> 5, lane = threadIdx.x & 31;
    int j = blockIdx.x * 16 + warp * 2;
    const float4* wa = (const float4*)(w + ((size_t)l * FFN + j) * HIDN);
    const float4* wb = wa + 512;
    float4 r = dot4_smem<512>(wa, wb, xs, lane);
    if (lane == 0) {
        g_h[0][j]     = gelu_exact(r.x); g_h[1][j]     = gelu_exact(r.y);
        g_h[0][j + 1] = gelu_exact(r.z); g_h[1][j + 1] = gelu_exact(r.w);
    }
}

// batch-split dual-row ffn2: grid (128, 2), block 256, 32KB dyn smem
__global__ void __launch_bounds__(256, 4)
k_ffn2(const float* __restrict__ w, int l) {
    extern __shared__ float4 hs[];           // 2048 float4 = 32KB (one batch)
    int b = blockIdx.y;
    const float4* hsrc = (const float4*)g_h[b];
    for (int i = threadIdx.x; i < 2048; i += 256) hs[i] = hsrc[i];
    __syncthreads();
    int warp = threadIdx.x >> 5, lane = threadIdx.x & 31;
    int j = blockIdx.x * 16 + warp * 2;
    const float4* wa = (const float4*)(w + ((size_t)l * HIDN + j) * FFN);
    const float4* wb = wa + 2048;
    float a = 0.f, c = 0.f;
    #pragma unroll 4
    for (int i = lane; i < 2048; i += 32) {
        float4 u = hs[i];
        float4 p = wa[i];
        float4 q = wb[i];
        a += p.x*u.x + p.y*u.y + p.z*u.z + p.w*u.w;
        c += q.x*u.x + q.y*u.y + q.z*u.z + q.w*u.w;
    }
    #pragma unroll
    for (int off = 16; off > 0; off >>= 1) {
        a += __shfl_down_sync(0xffffffffu, a, off);
        c += __shfl_down_sync(0xffffffffu, c, off);
    }
    if (lane == 0) { g_x[b][j] += a; g_x[b][j + 1] += c; }
}

// ============================================================
// LM head (LN fused) + final softmax
// ============================================================
__global__ void __launch_bounds__(256, 4)
k_lmhead(const float* __restrict__ w,
         const float* __restrict__ gam, const float* __restrict__ bet,
         float* __restrict__ out) {
    __shared__ __align__(16) float4 xs[1024];
    stage_ln(xs, gam, bet);
    int warp = threadIdx.x >> 5, lane = threadIdx.x & 31;
    int j = blockIdx.x * 16 + warp * 2;
    const float4* wa = (const float4*)(w + (size_t)j * HIDN);
    const float4* wb = wa + 512;
    float4 r = dot4_smem<512>(wa, wb, xs, lane);
    if (lane == 0) {
        out[j]     = r.x; out[(size_t)VV + j]     = r.y;
        out[j + 1] = r.z; out[(size_t)VV + j + 1] = r.w;
    }
}

__global__ void k_softmax(float* __restrict__ out) {
    int b = blockIdx.x;
    float* o = out + (size_t)b * VV;
    int tid = threadIdx.x;               // 1024
    __shared__ float red[1024];
    float m = -1e30f;
    for (int i = tid; i < VV; i += 1024) m = fmaxf(m, o[i]);
    red[tid] = m; __syncthreads();
    for (int off = 512; off > 0; off >>= 1) { if (tid < off) red[tid] = fmaxf(red[tid], red[tid + off]); __syncthreads(); }
    float mb = red[0];
    __syncthreads();
    float s = 0.f;
    for (int i = tid; i < VV; i += 1024) s += expf(o[i] - mb);
    red[tid] = s; __syncthreads();
    for (int off = 512; off > 0; off >>= 1) { if (tid < off) red[tid] += red[tid + off]; __syncthreads(); }
    float inv = 1.0f / red[0];
    __syncthreads();
    for (int i = tid; i < VV; i += 1024) o[i] = expf(o[i] - mb) * inv;
}

// ============================================================
// launch (graph-capturable: kernel launches only)
// ============================================================
extern "C" void kernel_launch(void* const* d_in, const int* in_sizes, int n_in,
                              void* d_out, int out_size) {
    const float* x      = (const float*)d_in[0];
    const float* qkv_w  = (const float*)d_in[1];
    const float* ffn1_w = (const float*)d_in[2];
    const float* ffn2_w = (const float*)d_in[3];
    const float* out_w  = (const float*)d_in[4];
    const float* ln_g   = (const float*)d_in[5];
    const float* ln_b   = (const float*)d_in[6];
    const float* k_heap = (const float*)d_in[7];
    const float* v_heap = (const float*)d_in[8];
    const float* k_off  = (const float*)d_in[9];
    const float* v_off  = (const float*)d_in[10];
    const int*   pos    = (const int*)  d_in[11];
    float* out = (float*)d_out;

    cudaFuncSetAttribute(k_ffn2, cudaFuncAttributeMaxDynamicSharedMemorySize, 32768);

    k_init<<<BB, 256>>>(x, pos);

    for (int l = 0; l < LLN; l++) {
        k_qkv<<<384, 256>>>(qkv_w, ln_g, ln_b, l);
        { dim3 gs(NCHUNK, BB * NHH); k_flash<<<gs, 256>>>(k_heap, k_off, v_heap, v_off, l); }
        k_ffn1<<<512, 256>>>(ffn1_w, ln_g, ln_b, l);
        { dim3 gf(128, BB); k_ffn2<<<gf, 256, 32768>>>(ffn2_w, l); }
    }

    k_lmhead<<<2000, 256>>>(out_w, ln_g, ln_b, out);
    k_softmax<<<BB, 1024>>>(out);
}

// round 7
// speedup vs baseline: 1.0873x; 1.0873x over previous
#include <cuda_runtime.h>
#include <math.h>
#include <stdint.h>

// ---- problem constants ----
#define BB    2
#define HIDN  2048
#define NHH   16
#define LLN   8
#define VV    32000
#define DDIM  128
#define OFFN  1024
#define RRES  1025
#define PHEAP 11272
#define NK    2049
#define FFN   8192
#define SSEQ  2048
#define NCHUNK 17

// ---- device scratch (allocation-free) ----
__device__ __align__(16) float g_x [BB][HIDN];
__device__ __align__(16) float g_q [BB][NHH][DDIM];
__device__ __align__(16) float g_kscr[LLN][BB][NHH][DDIM];
__device__ __align__(16) float g_vscr[LLN][BB][NHH][DDIM];
__device__ __align__(16) float g_h[BB][FFN];
__device__ float g_pm[NCHUNK][BB * NHH];
__device__ float g_ps[NCHUNK][BB * NHH];
__device__ __align__(16) float g_po[NCHUNK][BB * NHH][DDIM];
__device__ unsigned int g_cnt[BB * NHH];   // zero-init; self-resetting

// ============================================================
// x = x + sinusoidal PE(pos)
// ============================================================
__global__ void k_init(const float* __restrict__ x, const int* __restrict__ posp) {
    int b = blockIdx.x;
    float pos = (float)(*posp);
    for (int e = threadIdx.x; e < HIDN; e += blockDim.x) {
        int i = e >> 1;
        float div = expf(-logf(10000.0f) * (2.0f * (float)i) / (float)HIDN);
        float ang = pos * div;
        float pe = (e & 1) ? cosf(ang) : sinf(ang);
        g_x[b][e] = x[(size_t)b * HIDN + e] + pe;
    }
}

// ============================================================
// LN prologue (warp-shuffle, 3 barriers). block = 256 threads.
// xs layout: [0,512) = batch0 float4, [512,1024) = batch1 float4.
// ============================================================
__device__ __forceinline__ void stage_ln(float4* xs,
                                         const float* __restrict__ gam,
                                         const float* __restrict__ bet) {
    int tid = threadIdx.x, lane = tid & 31, warp = tid >> 5;
    __shared__ float4 wred[8];
    __shared__ float4 stats;   // mean0, rstd0, mean1, rstd1
    const float4* x0 = (const float4*)g_x[0];
    const float4* x1 = (const float4*)g_x[1];
    float4 a0 = x0[tid], a1 = x0[tid + 256];
    float4 b0 = x1[tid], b1 = x1[tid + 256];
    float s0 = a0.x + a0.y + a0.z + a0.w + a1.x + a1.y + a1.z + a1.w;
    float s1 = b0.x + b0.y + b0.z + b0.w + b1.x + b1.y + b1.z + b1.w;
    float q0 = a0.x*a0.x + a0.y*a0.y + a0.z*a0.z + a0.w*a0.w
             + a1.x*a1.x + a1.y*a1.y + a1.z*a1.z + a1.w*a1.w;
    float q1 = b0.x*b0.x + b0.y*b0.y + b0.z*b0.z + b0.w*b0.w
             + b1.x*b1.x + b1.y*b1.y + b1.z*b1.z + b1.w*b1.w;
    #pragma unroll
    for (int off = 16; off > 0; off >>= 1) {
        s0 += __shfl_down_sync(0xffffffffu, s0, off);
        q0 += __shfl_down_sync(0xffffffffu, q0, off);
        s1 += __shfl_down_sync(0xffffffffu, s1, off);
        q1 += __shfl_down_sync(0xffffffffu, q1, off);
    }
    if (lane == 0) wred[warp] = make_float4(s0, q0, s1, q1);
    __syncthreads();
    if (warp == 0) {
        float4 v = wred[lane & 7];
        float t0 = v.x, t1 = v.y, t2 = v.z, t3 = v.w;
        #pragma unroll
        for (int off = 4; off > 0; off >>= 1) {
            t0 += __shfl_down_sync(0xffffffffu, t0, off, 8);
            t1 += __shfl_down_sync(0xffffffffu, t1, off, 8);
            t2 += __shfl_down_sync(0xffffffffu, t2, off, 8);
            t3 += __shfl_down_sync(0xffffffffu, t3, off, 8);
        }
        if (lane == 0) {
            float mean0 = t0 * (1.0f / HIDN);
            float mean1 = t2 * (1.0f / HIDN);
            float var0  = t1 * (1.0f / HIDN) - mean0 * mean0;
            float var1  = t3 * (1.0f / HIDN) - mean1 * mean1;
            stats = make_float4(mean0, rsqrtf(var0 + 1e-5f),
                                mean1, rsqrtf(var1 + 1e-5f));
        }
    }
    __syncthreads();
    float4 st = stats;
    const float4* g4 = (const float4*)gam;
    const float4* e4 = (const float4*)bet;
    float4 ga = g4[tid], gb = g4[tid + 256];
    float4 ea = e4[tid], eb = e4[tid + 256];
    xs[tid] = make_float4((a0.x - st.x) * st.y * ga.x + ea.x,
                          (a0.y - st.x) * st.y * ga.y + ea.y,
                          (a0.z - st.x) * st.y * ga.z + ea.z,
                          (a0.w - st.x) * st.y * ga.w + ea.w);
    xs[tid + 256] = make_float4((a1.x - st.x) * st.y * gb.x + eb.x,
                                (a1.y - st.x) * st.y * gb.y + eb.y,
                                (a1.z - st.x) * st.y * gb.z + eb.z,
                                (a1.w - st.x) * st.y * gb.w + eb.w);
    xs[512 + tid] = make_float4((b0.x - st.z) * st.w * ga.x + ea.x,
                                (b0.y - st.z) * st.w * ga.y + ea.y,
                                (b0.z - st.z) * st.w * ga.z + ea.z,
                                (b0.w - st.z) * st.w * ga.w + ea.w);
    xs[512 + tid + 256] = make_float4((b1.x - st.z) * st.w * gb.x + eb.x,
                                      (b1.y - st.z) * st.w * gb.y + eb.y,
                                      (b1.z - st.z) * st.w * gb.z + eb.z,
                                      (b1.w - st.z) * st.w * gb.w + eb.w);
    __syncthreads();
}

// warp GEMV: one weight row (gmem stream only) vs two smem vectors
template <int N4>
__device__ __forceinline__ float2 dot2_smem(const float4* __restrict__ w4,
                                            const float4* xs, int lane) {
    float a0 = 0.f, a1 = 0.f;
    #pragma unroll 8
    for (int i = lane; i < N4; i += 32) {
        float4 wv = w4[i];
        float4 u = xs[i];
        float4 v = xs[N4 + i];
        a0 += wv.x*u.x + wv.y*u.y + wv.z*u.z + wv.w*u.w;
        a1 += wv.x*v.x + wv.y*v.y + wv.z*v.z + wv.w*v.w;
    }
    #pragma unroll
    for (int off = 16; off > 0; off >>= 1) {
        a0 += __shfl_down_sync(0xffffffffu, a0, off);
        a1 += __shfl_down_sync(0xffffffffu, a1, off);
    }
    return make_float2(a0, a1);
}

// ============================================================
// QKV projection (LN fused, persistent): 6144 rows, 8 rows/chunk
// grid 384, each block does 2 chunks
// ============================================================
__global__ void __launch_bounds__(256, 5)
k_qkv(const float* __restrict__ qkv_w,
      const float* __restrict__ gam, const float* __restrict__ bet, int l) {
    __shared__ __align__(16) float4 xs[1024];
    stage_ln(xs, gam, bet);
    int warp = threadIdx.x >> 5, lane = threadIdx.x & 31;
    for (int chunk = blockIdx.x; chunk < 768; chunk += gridDim.x) {
        int j = chunk * 8 + warp;
        const float4* w4 = (const float4*)(qkv_w + ((size_t)l * 3 * HIDN + j) * HIDN);
        float2 r = dot2_smem<512>(w4, xs, lane);
        if (lane == 0) {
            int h = j / 384, c = j % 384;
            if (c < 128)      { g_q[0][h][c] = r.x;            g_q[1][h][c] = r.y; }
            else if (c < 256) { g_kscr[l][0][h][c-128] = r.x;  g_kscr[l][1][h][c-128] = r.y; }
            else              { g_vscr[l][0][h][c-256] = r.x;  g_vscr[l][1][h][c-256] = r.y; }
        }
    }
}

// ============================================================
// KV row addressing with scatter-write overrides
// ============================================================
__device__ __forceinline__ const float* kv_row(int l, int b, int h, int k,
        const float* __restrict__ heap, const float* __restrict__ off,
        const float (*scr)[BB][NHH][DDIM]) {
    if (l == 0) {
        if (k == SSEQ) return scr[0][b][h];
        return heap + (((size_t)(b * NHH + h)) * PHEAP + (size_t)k) * DDIM;
    }
    if (k < RRES) {
        if (k == 1023 && l >= 2) return scr[l - 2][b][h];
        return heap + (((size_t)(b * NHH + h)) * PHEAP + (size_t)(l - 1) * RRES + (size_t)k) * DDIM;
    }
    return off + (((((size_t)(l - 1)) * BB + b) * NHH + h) * OFFN + (size_t)(k - RRES)) * DDIM;
}

// ============================================================
// fused flash-decode partial + last-block combine
// grid (17, 32), block 256
// ============================================================
__global__ void k_flash(const float* __restrict__ kh, const float* __restrict__ ko,
                        const float* __restrict__ vh, const float* __restrict__ vo, int l) {
    int bh = blockIdx.y; int b = bh >> 4, h = bh & 15;
    int base = blockIdx.x * 128;
    int tid = threadIdx.x, warp = tid >> 5, lane = tid & 31;
    __shared__ float part[128][33];
    __shared__ float sc[128];
    __shared__ float red[128];
    __shared__ __align__(16) float4 vred[8][32];
    __shared__ __align__(16) float q_s[DDIM];
    __shared__ bool is_last;
    if (tid < DDIM) q_s[tid] = g_q[b][h][tid];
    __syncthreads();
    float4 q4 = ((const float4*)q_s)[lane];

    // ---- K phase: warp handles 16 independent rows ----
    #pragma unroll 4
    for (int i = 0; i < 16; i++) {
        int r = warp * 16 + i, k = base + r;
        float p = 0.f;
        if (k < NK) {
            const float* kr = kv_row(l, b, h, k, kh, ko, g_kscr);
            float4 kk = ((const float4*)kr)[lane];
            p = q4.x*kk.x + q4.y*kk.y + q4.z*kk.z + q4.w*kk.w;
        }
        part[r][lane] = p;
    }
    __syncthreads();

    // ---- score reduce (conflict-free, stride 33) ----
    if (tid < 128) {
        float s = 0.f;
        #pragma unroll
        for (int i = 0; i < 32; i++) s += part[tid][i];
        s *= 0.088388347648318447f;
        if (base + tid >= NK) s = -1e30f;
        sc[tid] = s;
    }
    __syncthreads();
    if (tid < 64) red[tid] = fmaxf(sc[tid], sc[tid + 64]);
    __syncthreads();
    if (tid < 32) {
        float m = fmaxf(red[tid], red[tid + 32]);
        #pragma unroll
        for (int off = 16; off > 0; off >>= 1)
            m = fmaxf(m, __shfl_down_sync(0xffffffffu, m, off));
        if (tid == 0) red[0] = m;
    }
    __syncthreads();
    float mloc = red[0];
    __syncthreads();
    if (tid < 128) sc[tid] = expf(sc[tid] - mloc);
    __syncthreads();
    if (tid < 64) red[tid] = sc[tid] + sc[tid + 64];
    __syncthreads();
    if (tid < 32) {
        float s = red[tid] + red[tid + 32];
        #pragma unroll
        for (int off = 16; off > 0; off >>= 1)
            s += __shfl_down_sync(0xffffffffu, s, off);
        if (tid == 0) red[0] = s;
    }
    __syncthreads();
    float ssum = red[0];

    // ---- V phase ----
    float4 acc = make_float4(0.f, 0.f, 0.f, 0.f);
    #pragma unroll 4
    for (int i = 0; i < 16; i++) {
        int r = warp * 16 + i, k = base + r;
        if (k < NK) {
            const float* vr = kv_row(l, b, h, k, vh, vo, g_vscr);
            float4 v4 = ((const float4*)vr)[lane];
            float pr = sc[r];
            acc.x += pr * v4.x; acc.y += pr * v4.y;
            acc.z += pr * v4.z; acc.w += pr * v4.w;
        }
    }
    vred[warp][lane] = acc;
    __syncthreads();
    if (tid < 128) {
        int li = tid >> 2, c = tid & 3;
        float o = 0.f;
        #pragma unroll
        for (int w2 = 0; w2 < 8; w2++) o += ((const float*)&vred[w2][li])[c];
        g_po[blockIdx.x][bh][tid] = o;
    }
    if (tid == 0) { g_pm[blockIdx.x][bh] = mloc; g_ps[blockIdx.x][bh] = ssum; }

    // ---- last block for this (b,h) combines all 17 partials ----
    __threadfence();
    if (tid == 0) {
        unsigned int v = atomicAdd(&g_cnt[bh], 1u);
        is_last = (v == NCHUNK - 1);
    }
    __syncthreads();
    if (!is_last) return;
    __threadfence();                    // acquire partials from other blocks
    if (tid == 0) g_cnt[bh] = 0;        // reset for next layer / graph replay
    if (tid < 128) {
        float m = -1e30f;
        #pragma unroll
        for (int c = 0; c < NCHUNK; c++) m = fmaxf(m, g_pm[c][bh]);
        float S = 0.f, o = 0.f;
        #pragma unroll
        for (int c = 0; c < NCHUNK; c++) {
            float w = expf(g_pm[c][bh] - m);
            S += g_ps[c][bh] * w;
            o += g_po[c][bh][tid] * w;
        }
        g_x[b][h * DDIM + tid] += o / S;
    }
}

// ============================================================
// FFN
// ============================================================
__device__ __forceinline__ float gelu_exact(float x) {
    return 0.5f * x * (1.0f + erff(x * 0.70710678118654752f));
}

// persistent: grid 512, 1024 chunks of 8 rows
__global__ void __launch_bounds__(256, 5)
k_ffn1(const float* __restrict__ w,
       const float* __restrict__ gam, const float* __restrict__ bet, int l) {
    __shared__ __align__(16) float4 xs[1024];
    stage_ln(xs, gam, bet);
    int warp = threadIdx.x >> 5, lane = threadIdx.x & 31;
    for (int chunk = blockIdx.x; chunk < 1024; chunk += gridDim.x) {
        int j = chunk * 8 + warp;
        const float4* w4 = (const float4*)(w + ((size_t)l * FFN + j) * HIDN);
        float2 r = dot2_smem<512>(w4, xs, lane);
        if (lane == 0) { g_h[0][j] = gelu_exact(r.x); g_h[1][j] = gelu_exact(r.y); }
    }
}

__global__ void k_ffn2(const float* __restrict__ w, int l) {
    extern __shared__ float4 hs[];           // 4096 float4 = 64KB (both batches)
    const float4* hsrc = (const float4*)g_h[0];
    for (int i = threadIdx.x; i < 4096; i += 256) hs[i] = hsrc[i];
    __syncthreads();
    int warp = threadIdx.x >> 5, lane = threadIdx.x & 31;
    int j = blockIdx.x * 8 + warp;
    const float4* w4 = (const float4*)(w + ((size_t)l * HIDN + j) * FFN);
    float2 r = dot2_smem<2048>(w4, hs, lane);
    if (lane == 0) { g_x[0][j] += r.x; g_x[1][j] += r.y; }
}

// ============================================================
// LM head (LN fused, persistent) + final softmax
// grid 592, 4000 chunks of 8 rows
// ============================================================
__global__ void __launch_bounds__(256, 5)
k_lmhead(const float* __restrict__ w,
         const float* __restrict__ gam, const float* __restrict__ bet,
         float* __restrict__ out) {
    __shared__ __align__(16) float4 xs[1024];
    stage_ln(xs, gam, bet);
    int warp = threadIdx.x >> 5, lane = threadIdx.x & 31;
    for (int chunk = blockIdx.x; chunk < 4000; chunk += gridDim.x) {
        int j = chunk * 8 + warp;
        const float4* w4 = (const float4*)(w + (size_t)j * HIDN);
        float2 r = dot2_smem<512>(w4, xs, lane);
        if (lane == 0) { out[j] = r.x; out[(size_t)VV + j] = r.y; }
    }
}

__global__ void k_softmax(float* __restrict__ out) {
    int b = blockIdx.x;
    float* o = out + (size_t)b * VV;
    int tid = threadIdx.x;               // 1024
    __shared__ float red[1024];
    float m = -1e30f;
    for (int i = tid; i < VV; i += 1024) m = fmaxf(m, o[i]);
    red[tid] = m; __syncthreads();
    for (int off = 512; off > 0; off >>= 1) { if (tid < off) red[tid] = fmaxf(red[tid], red[tid + off]); __syncthreads(); }
    float mb = red[0];
    __syncthreads();
    float s = 0.f;
    for (int i = tid; i < VV; i += 1024) s += expf(o[i] - mb);
    red[tid] = s; __syncthreads();
    for (int off = 512; off > 0; off >>= 1) { if (tid < off) red[tid] += red[tid + off]; __syncthreads(); }
    float inv = 1.0f / red[0];
    __syncthreads();
    for (int i = tid; i < VV; i += 1024) o[i] = expf(o[i] - mb) * inv;
}

// ============================================================
// launch (graph-capturable: kernel launches only)
// ============================================================
extern "C" void kernel_launch(void* const* d_in, const int* in_sizes, int n_in,
                              void* d_out, int out_size) {
    const float* x      = (const float*)d_in[0];
    const float* qkv_w  = (const float*)d_in[1];
    const float* ffn1_w = (const float*)d_in[2];
    const float* ffn2_w = (const float*)d_in[3];
    const float* out_w  = (const float*)d_in[4];
    const float* ln_g   = (const float*)d_in[5];
    const float* ln_b   = (const float*)d_in[6];
    const float* k_heap = (const float*)d_in[7];
    const float* v_heap = (const float*)d_in[8];
    const float* k_off  = (const float*)d_in[9];
    const float* v_off  = (const float*)d_in[10];
    const int*   pos    = (const int*)  d_in[11];
    float* out = (float*)d_out;

    cudaFuncSetAttribute(k_ffn2, cudaFuncAttributeMaxDynamicSharedMemorySize, 65536);

    k_init<<<BB, 256>>>(x, pos);

    for (int l = 0; l < LLN; l++) {
        k_qkv<<<384, 256>>>(qkv_w, ln_g, ln_b, l);
        { dim3 gs(NCHUNK, BB * NHH); k_flash<<<gs, 256>>>(k_heap, k_off, v_heap, v_off, l); }
        k_ffn1<<<512, 256>>>(ffn1_w, ln_g, ln_b, l);
        k_ffn2<<<256, 256, 65536>>>(ffn2_w, l);
    }

    k_lmhead<<<592, 256>>>(out_w, ln_g, ln_b, out);
    k_softmax<<<BB, 1024>>>(out);
}

// round 8
// speedup vs baseline: 1.1223x; 1.0322x over previous
#include <cuda_runtime.h>
#include <math.h>
#include <stdint.h>

// ---- problem constants ----
#define BB    2
#define HIDN  2048
#define NHH   16
#define LLN   8
#define VV    32000
#define DDIM  128
#define OFFN  1024
#define RRES  1025
#define PHEAP 11272
#define NK    2049
#define FFN   8192
#define SSEQ  2048
#define NCHUNK 17

// ---- device scratch (allocation-free) ----
__device__ __align__(16) float g_x [BB][HIDN];
__device__ __align__(16) float g_q [BB][NHH][DDIM];
__device__ __align__(16) float g_kscr[LLN][BB][NHH][DDIM];
__device__ __align__(16) float g_vscr[LLN][BB][NHH][DDIM];
__device__ __align__(16) float g_h[BB][FFN];
__device__ float g_pm[NCHUNK][BB * NHH];
__device__ float g_ps[NCHUNK][BB * NHH];
__device__ __align__(16) float g_po[NCHUNK][BB * NHH][DDIM];
__device__ unsigned int g_cnt[BB * NHH];   // zero-init; self-resetting

// ============================================================
// x = x + sinusoidal PE(pos)
// ============================================================
__global__ void k_init(const float* __restrict__ x, const int* __restrict__ posp) {
    int b = blockIdx.x;
    float pos = (float)(*posp);
    for (int e = threadIdx.x; e < HIDN; e += blockDim.x) {
        int i = e >> 1;
        float div = expf(-logf(10000.0f) * (2.0f * (float)i) / (float)HIDN);
        float ang = pos * div;
        float pe = (e & 1) ? cosf(ang) : sinf(ang);
        g_x[b][e] = x[(size_t)b * HIDN + e] + pe;
    }
}

// ============================================================
// LN prologue (warp-shuffle, 3 barriers). block = 256 threads.
// xs layout: [0,512) = batch0 float4, [512,1024) = batch1 float4.
// ============================================================
__device__ __forceinline__ void stage_ln(float4* xs,
                                         const float* __restrict__ gam,
                                         const float* __restrict__ bet) {
    int tid = threadIdx.x, lane = tid & 31, warp = tid >> 5;
    __shared__ float4 wred[8];
    __shared__ float4 stats;   // mean0, rstd0, mean1, rstd1
    const float4* x0 = (const float4*)g_x[0];
    const float4* x1 = (const float4*)g_x[1];
    float4 a0 = x0[tid], a1 = x0[tid + 256];
    float4 b0 = x1[tid], b1 = x1[tid + 256];
    float s0 = a0.x + a0.y + a0.z + a0.w + a1.x + a1.y + a1.z + a1.w;
    float s1 = b0.x + b0.y + b0.z + b0.w + b1.x + b1.y + b1.z + b1.w;
    float q0 = a0.x*a0.x + a0.y*a0.y + a0.z*a0.z + a0.w*a0.w
             + a1.x*a1.x + a1.y*a1.y + a1.z*a1.z + a1.w*a1.w;
    float q1 = b0.x*b0.x + b0.y*b0.y + b0.z*b0.z + b0.w*b0.w
             + b1.x*b1.x + b1.y*b1.y + b1.z*b1.z + b1.w*b1.w;
    #pragma unroll
    for (int off = 16; off > 0; off >>= 1) {
        s0 += __shfl_down_sync(0xffffffffu, s0, off);
        q0 += __shfl_down_sync(0xffffffffu, q0, off);
        s1 += __shfl_down_sync(0xffffffffu, s1, off);
        q1 += __shfl_down_sync(0xffffffffu, q1, off);
    }
    if (lane == 0) wred[warp] = make_float4(s0, q0, s1, q1);
    __syncthreads();
    if (warp == 0) {
        float4 v = wred[lane & 7];
        float t0 = v.x, t1 = v.y, t2 = v.z, t3 = v.w;
        #pragma unroll
        for (int off = 4; off > 0; off >>= 1) {
            t0 += __shfl_down_sync(0xffffffffu, t0, off, 8);
            t1 += __shfl_down_sync(0xffffffffu, t1, off, 8);
            t2 += __shfl_down_sync(0xffffffffu, t2, off, 8);
            t3 += __shfl_down_sync(0xffffffffu, t3, off, 8);
        }
        if (lane == 0) {
            float mean0 = t0 * (1.0f / HIDN);
            float mean1 = t2 * (1.0f / HIDN);
            float var0  = t1 * (1.0f / HIDN) - mean0 * mean0;
            float var1  = t3 * (1.0f / HIDN) - mean1 * mean1;
            stats = make_float4(mean0, rsqrtf(var0 + 1e-5f),
                                mean1, rsqrtf(var1 + 1e-5f));
        }
    }
    __syncthreads();
    float4 st = stats;
    const float4* g4 = (const float4*)gam;
    const float4* e4 = (const float4*)bet;
    float4 ga = g4[tid], gb = g4[tid + 256];
    float4 ea = e4[tid], eb = e4[tid + 256];
    xs[tid] = make_float4((a0.x - st.x) * st.y * ga.x + ea.x,
                          (a0.y - st.x) * st.y * ga.y + ea.y,
                          (a0.z - st.x) * st.y * ga.z + ea.z,
                          (a0.w - st.x) * st.y * ga.w + ea.w);
    xs[tid + 256] = make_float4((a1.x - st.x) * st.y * gb.x + eb.x,
                                (a1.y - st.x) * st.y * gb.y + eb.y,
                                (a1.z - st.x) * st.y * gb.z + eb.z,
                                (a1.w - st.x) * st.y * gb.w + eb.w);
    xs[512 + tid] = make_float4((b0.x - st.z) * st.w * ga.x + ea.x,
                                (b0.y - st.z) * st.w * ga.y + ea.y,
                                (b0.z - st.z) * st.w * ga.z + ea.z,
                                (b0.w - st.z) * st.w * ga.w + ea.w);
    xs[512 + tid + 256] = make_float4((b1.x - st.z) * st.w * gb.x + eb.x,
                                      (b1.y - st.z) * st.w * gb.y + eb.y,
                                      (b1.z - st.z) * st.w * gb.z + eb.z,
                                      (b1.w - st.z) * st.w * gb.w + eb.w);
    __syncthreads();
}

// ============================================================
// cp.async helpers
// ============================================================
__device__ __forceinline__ void cp16(uint32_t dst, const void* src) {
    asm volatile("cp.async.cg.shared.global [%0], [%1], 16;"
                 :: "r"(dst), "l"(src) : "memory");
}
__device__ __forceinline__ void cp_commit() {
    asm volatile("cp.async.commit_group;" ::: "memory");
}
__device__ __forceinline__ void cp_wait2() {
    asm volatile("cp.async.wait_group 2;" ::: "memory");
}

// ============================================================
// dual-row cp.async-pipelined GEMV core.
// Warp computes rows A,B vs both staged x vectors.
// wslice: this warp's smem ring = 3 stages x 2 rows x 32 float4 (192 float4)
// Segment = 32 float4 (512B per row). 3-stage ring, 2 segs in flight.
// Returns (A.x0, A.x1, B.x0, B.x1) valid on lane 0.
// ============================================================
template <int NF4>
__device__ __forceinline__ float4 dual_dot_pipe(const float4* __restrict__ wA,
                                                const float4* __restrict__ wB,
                                                const float4* xs,
                                                float4* wslice, int lane) {
    constexpr int NSEG = NF4 / 32;
    uint32_t sb = (uint32_t)__cvta_generic_to_shared(wslice);
    // prologue: issue segs 0,1 into stages 0,1
    #pragma unroll
    for (int p = 0; p < 2; p++) {
        cp16(sb + ((p * 64 + lane) << 4),      wA + p * 32 + lane);
        cp16(sb + ((p * 64 + 32 + lane) << 4), wB + p * 32 + lane);
        cp_commit();
    }
    float a00 = 0.f, a01 = 0.f, a10 = 0.f, a11 = 0.f;
    for (int s = 0; s < NSEG; s++) {
        int nx = s + 2;
        if (nx < NSEG) {
            int stn = nx % 3;
            cp16(sb + ((stn * 64 + lane) << 4),      wA + nx * 32 + lane);
            cp16(sb + ((stn * 64 + 32 + lane) << 4), wB + nx * 32 + lane);
        }
        cp_commit();          // empty groups near the end keep the count uniform
        cp_wait2();           // oldest (seg s) is complete
        int st = s % 3;
        float4 wa = wslice[st * 64 + lane];
        float4 wb = wslice[st * 64 + 32 + lane];
        float4 xu = xs[s * 32 + lane];
        float4 xv = xs[NF4 + s * 32 + lane];
        a00 += wa.x*xu.x + wa.y*xu.y + wa.z*xu.z + wa.w*xu.w;
        a01 += wa.x*xv.x + wa.y*xv.y + wa.z*xv.z + wa.w*xv.w;
        a10 += wb.x*xu.x + wb.y*xu.y + wb.z*xu.z + wb.w*xu.w;
        a11 += wb.x*xv.x + wb.y*xv.y + wb.z*xv.z + wb.w*xv.w;
    }
    #pragma unroll
    for (int off = 16; off > 0; off >>= 1) {
        a00 += __shfl_down_sync(0xffffffffu, a00, off);
        a01 += __shfl_down_sync(0xffffffffu, a01, off);
        a10 += __shfl_down_sync(0xffffffffu, a10, off);
        a11 += __shfl_down_sync(0xffffffffu, a11, off);
    }
    return make_float4(a00, a01, a10, a11);
}

__device__ __forceinline__ void route_qkv(int j, float v0, float v1, int l) {
    int h = j / 384, c = j % 384;
    if (c < 128)      { g_q[0][h][c] = v0;             g_q[1][h][c] = v1; }
    else if (c < 256) { g_kscr[l][0][h][c-128] = v0;   g_kscr[l][1][h][c-128] = v1; }
    else              { g_vscr[l][0][h][c-256] = v0;   g_vscr[l][1][h][c-256] = v1; }
}

// ============================================================
// QKV projection (LN fused): 6144 rows = 384 chunks of 16, grid 384
// ============================================================
__global__ void __launch_bounds__(256, 4)
k_qkv(const float* __restrict__ qkv_w,
      const float* __restrict__ gam, const float* __restrict__ bet, int l) {
    __shared__ __align__(16) float4 xs[1024];
    __shared__ __align__(16) float4 wbuf[8 * 192];
    stage_ln(xs, gam, bet);
    int warp = threadIdx.x >> 5, lane = threadIdx.x & 31;
    int j = blockIdx.x * 16 + warp * 2;
    const float4* wA = (const float4*)(qkv_w + ((size_t)l * 3 * HIDN + j) * HIDN);
    const float4* wB = wA + 512;
    float4 r = dual_dot_pipe<512>(wA, wB, xs, wbuf + warp * 192, lane);
    if (lane == 0) {
        route_qkv(j,     r.x, r.y, l);
        route_qkv(j + 1, r.z, r.w, l);
    }
}

// ============================================================
// KV row addressing with scatter-write overrides
// ============================================================
__device__ __forceinline__ const float* kv_row(int l, int b, int h, int k,
        const float* __restrict__ heap, const float* __restrict__ off,
        const float (*scr)[BB][NHH][DDIM]) {
    if (l == 0) {
        if (k == SSEQ) return scr[0][b][h];
        return heap + (((size_t)(b * NHH + h)) * PHEAP + (size_t)k) * DDIM;
    }
    if (k < RRES) {
        if (k == 1023 && l >= 2) return scr[l - 2][b][h];
        return heap + (((size_t)(b * NHH + h)) * PHEAP + (size_t)(l - 1) * RRES + (size_t)k) * DDIM;
    }
    return off + (((((size_t)(l - 1)) * BB + b) * NHH + h) * OFFN + (size_t)(k - RRES)) * DDIM;
}

// ============================================================
// fused flash-decode partial + last-block combine
// grid (17, 32), block 256
// ============================================================
__global__ void k_flash(const float* __restrict__ kh, const float* __restrict__ ko,
                        const float* __restrict__ vh, const float* __restrict__ vo, int l) {
    int bh = blockIdx.y; int b = bh >> 4, h = bh & 15;
    int base = blockIdx.x * 128;
    int tid = threadIdx.x, warp = tid >> 5, lane = tid & 31;
    __shared__ float part[128][33];
    __shared__ float sc[128];
    __shared__ float red[128];
    __shared__ __align__(16) float4 vred[8][32];
    __shared__ __align__(16) float q_s[DDIM];
    __shared__ bool is_last;
    if (tid < DDIM) q_s[tid] = g_q[b][h][tid];
    __syncthreads();
    float4 q4 = ((const float4*)q_s)[lane];

    // ---- K phase: warp handles 16 independent rows ----
    #pragma unroll 4
    for (int i = 0; i < 16; i++) {
        int r = warp * 16 + i, k = base + r;
        float p = 0.f;
        if (k < NK) {
            const float* kr = kv_row(l, b, h, k, kh, ko, g_kscr);
            float4 kk = ((const float4*)kr)[lane];
            p = q4.x*kk.x + q4.y*kk.y + q4.z*kk.z + q4.w*kk.w;
        }
        part[r][lane] = p;
    }
    __syncthreads();

    // ---- score reduce (conflict-free, stride 33) ----
    if (tid < 128) {
        float s = 0.f;
        #pragma unroll
        for (int i = 0; i < 32; i++) s += part[tid][i];
        s *= 0.088388347648318447f;
        if (base + tid >= NK) s = -1e30f;
        sc[tid] = s;
    }
    __syncthreads();
    if (tid < 64) red[tid] = fmaxf(sc[tid], sc[tid + 64]);
    __syncthreads();
    if (tid < 32) {
        float m = fmaxf(red[tid], red[tid + 32]);
        #pragma unroll
        for (int off = 16; off > 0; off >>= 1)
            m = fmaxf(m, __shfl_down_sync(0xffffffffu, m, off));
        if (tid == 0) red[0] = m;
    }
    __syncthreads();
    float mloc = red[0];
    __syncthreads();
    if (tid < 128) sc[tid] = expf(sc[tid] - mloc);
    __syncthreads();
    if (tid < 64) red[tid] = sc[tid] + sc[tid + 64];
    __syncthreads();
    if (tid < 32) {
        float s = red[tid] + red[tid + 32];
        #pragma unroll
        for (int off = 16; off > 0; off >>= 1)
            s += __shfl_down_sync(0xffffffffu, s, off);
        if (tid == 0) red[0] = s;
    }
    __syncthreads();
    float ssum = red[0];

    // ---- V phase ----
    float4 acc = make_float4(0.f, 0.f, 0.f, 0.f);
    #pragma unroll 4
    for (int i = 0; i < 16; i++) {
        int r = warp * 16 + i, k = base + r;
        if (k < NK) {
            const float* vr = kv_row(l, b, h, k, vh, vo, g_vscr);
            float4 v4 = ((const float4*)vr)[lane];
            float pr = sc[r];
            acc.x += pr * v4.x; acc.y += pr * v4.y;
            acc.z += pr * v4.z; acc.w += pr * v4.w;
        }
    }
    vred[warp][lane] = acc;
    __syncthreads();
    if (tid < 128) {
        int li = tid >> 2, c = tid & 3;
        float o = 0.f;
        #pragma unroll
        for (int w2 = 0; w2 < 8; w2++) o += ((const float*)&vred[w2][li])[c];
        g_po[blockIdx.x][bh][tid] = o;
    }
    if (tid == 0) { g_pm[blockIdx.x][bh] = mloc; g_ps[blockIdx.x][bh] = ssum; }

    // ---- last block for this (b,h) combines all 17 partials ----
    __threadfence();
    if (tid == 0) {
        unsigned int v = atomicAdd(&g_cnt[bh], 1u);
        is_last = (v == NCHUNK - 1);
    }
    __syncthreads();
    if (!is_last) return;
    __threadfence();                    // acquire partials from other blocks
    if (tid == 0) g_cnt[bh] = 0;        // reset for next layer / graph replay
    if (tid < 128) {
        float m = -1e30f;
        #pragma unroll
        for (int c = 0; c < NCHUNK; c++) m = fmaxf(m, g_pm[c][bh]);
        float S = 0.f, o = 0.f;
        #pragma unroll
        for (int c = 0; c < NCHUNK; c++) {
            float w = expf(g_pm[c][bh] - m);
            S += g_ps[c][bh] * w;
            o += g_po[c][bh][tid] * w;
        }
        g_x[b][h * DDIM + tid] += o / S;
    }
}

// ============================================================
// FFN
// ============================================================
__device__ __forceinline__ float gelu_exact(float x) {
    return 0.5f * x * (1.0f + erff(x * 0.70710678118654752f));
}

// ffn1: 8192 rows = 512 chunks of 16, grid 512 (single wave @4/SM)
__global__ void __launch_bounds__(256, 4)
k_ffn1(const float* __restrict__ w,
       const float* __restrict__ gam, const float* __restrict__ bet, int l) {
    __shared__ __align__(16) float4 xs[1024];
    __shared__ __align__(16) float4 wbuf[8 * 192];
    stage_ln(xs, gam, bet);
    int warp = threadIdx.x >> 5, lane = threadIdx.x & 31;
    int j = blockIdx.x * 16 + warp * 2;
    const float4* wA = (const float4*)(w + ((size_t)l * FFN + j) * HIDN);
    const float4* wB = wA + 512;
    float4 r = dual_dot_pipe<512>(wA, wB, xs, wbuf + warp * 192, lane);
    if (lane == 0) {
        g_h[0][j]     = gelu_exact(r.x); g_h[1][j]     = gelu_exact(r.y);
        g_h[0][j + 1] = gelu_exact(r.z); g_h[1][j + 1] = gelu_exact(r.w);
    }
}

// ffn2: 2048 rows = 128 chunks of 16, grid 128; hs = 64KB dynamic smem
__global__ void __launch_bounds__(256, 2)
k_ffn2(const float* __restrict__ w, int l) {
    extern __shared__ float4 hs[];           // 4096 float4 = 64KB (both batches)
    __shared__ __align__(16) float4 wbuf[8 * 192];
    const float4* hsrc = (const float4*)g_h[0];
    for (int i = threadIdx.x; i < 4096; i += 256) hs[i] = hsrc[i];
    __syncthreads();
    int warp = threadIdx.x >> 5, lane = threadIdx.x & 31;
    int j = blockIdx.x * 16 + warp * 2;
    const float4* wA = (const float4*)(w + ((size_t)l * HIDN + j) * FFN);
    const float4* wB = wA + 2048;
    float4 r = dual_dot_pipe<2048>(wA, wB, hs, wbuf + warp * 192, lane);
    if (lane == 0) {
        g_x[0][j]     += r.x; g_x[1][j]     += r.y;
        g_x[0][j + 1] += r.z; g_x[1][j + 1] += r.w;
    }
}

// ============================================================
// LM head (LN fused): 32000 rows = 2000 chunks of 16, grid 500 x 4 chunks
// ============================================================
__global__ void __launch_bounds__(256, 4)
k_lmhead(const float* __restrict__ w,
         const float* __restrict__ gam, const float* __restrict__ bet,
         float* __restrict__ out) {
    __shared__ __align__(16) float4 xs[1024];
    __shared__ __align__(16) float4 wbuf[8 * 192];
    stage_ln(xs, gam, bet);
    int warp = threadIdx.x >> 5, lane = threadIdx.x & 31;
    for (int c = blockIdx.x; c < 2000; c += 500) {
        int j = c * 16 + warp * 2;
        const float4* wA = (const float4*)(w + (size_t)j * HIDN);
        const float4* wB = wA + 512;
        float4 r = dual_dot_pipe<512>(wA, wB, xs, wbuf + warp * 192, lane);
        if (lane == 0) {
            out[j]     = r.x; out[(size_t)VV + j]     = r.y;
            out[j + 1] = r.z; out[(size_t)VV + j + 1] = r.w;
        }
    }
}

__global__ void k_softmax(float* __restrict__ out) {
    int b = blockIdx.x;
    float* o = out + (size_t)b * VV;
    int tid = threadIdx.x;               // 1024
    __shared__ float red[1024];
    float m = -1e30f;
    for (int i = tid; i < VV; i += 1024) m = fmaxf(m, o[i]);
    red[tid] = m; __syncthreads();
    for (int off = 512; off > 0; off >>= 1) { if (tid < off) red[tid] = fmaxf(red[tid], red[tid + off]); __syncthreads(); }
    float mb = red[0];
    __syncthreads();
    float s = 0.f;
    for (int i = tid; i < VV; i += 1024) s += expf(o[i] - mb);
    red[tid] = s; __syncthreads();
    for (int off = 512; off > 0; off >>= 1) { if (tid < off) red[tid] += red[tid + off]; __syncthreads(); }
    float inv = 1.0f / red[0];
    __syncthreads();
    for (int i = tid; i < VV; i += 1024) o[i] = expf(o[i] - mb) * inv;
}

// ============================================================
// launch (graph-capturable: kernel launches only)
// ============================================================
extern "C" void kernel_launch(void* const* d_in, const int* in_sizes, int n_in,
                              void* d_out, int out_size) {
    const float* x      = (const float*)d_in[0];
    const float* qkv_w  = (const float*)d_in[1];
    const float* ffn1_w = (const float*)d_in[2];
    const float* ffn2_w = (const float*)d_in[3];
    const float* out_w  = (const float*)d_in[4];
    const float* ln_g   = (const float*)d_in[5];
    const float* ln_b   = (const float*)d_in[6];
    const float* k_heap = (const float*)d_in[7];
    const float* v_heap = (const float*)d_in[8];
    const float* k_off  = (const float*)d_in[9];
    const float* v_off  = (const float*)d_in[10];
    const int*   pos    = (const int*)  d_in[11];
    float* out = (float*)d_out;

    cudaFuncSetAttribute(k_ffn2, cudaFuncAttributeMaxDynamicSharedMemorySize, 65536);

    k_init<<<BB, 256>>>(x, pos);

    for (int l = 0; l < LLN; l++) {
        k_qkv<<<384, 256>>>(qkv_w, ln_g, ln_b, l);
        { dim3 gs(NCHUNK, BB * NHH); k_flash<<<gs, 256>>>(k_heap, k_off, v_heap, v_off, l); }
        k_ffn1<<<512, 256>>>(ffn1_w, ln_g, ln_b, l);
        k_ffn2<<<128, 256, 65536>>>(ffn2_w, l);
    }

    k_lmhead<<<500, 256>>>(out_w, ln_g, ln_b, out);
    k_softmax<<<BB, 1024>>>(out);
}